// round 4
// baseline (speedup 1.0000x reference)
#include <cuda_runtime.h>
#include <cuda_bf16.h>

// Problem constants (fixed shapes for BevPoolV2_8478265442577)
#define B_     1
#define N_CAM  6
#define D_BINS 118
#define HF     32
#define WF     88
#define C_     80
#define DZ     1
#define DY     128
#define DX     128

#define N_DEPTH (B_ * N_CAM * D_BINS * HF * WF)   // 1,993,728
#define N_FEAT  (B_ * N_CAM * HF * WF * C_)       // 1,351,680
#define N_PTS   1000000
#define S_      (DZ * DY * DX)                    // 16,384

// ---------------------------------------------------------------------------
// Zero-init the output (harness poisons d_out with 0xAA; empty bins must be 0)
// ---------------------------------------------------------------------------
__global__ void zero_kernel(float4* __restrict__ out, int n4) {
    int i = blockIdx.x * blockDim.x + threadIdx.x;
    int stride = gridDim.x * blockDim.x;
    for (; i < n4; i += stride)
        out[i] = make_float4(0.f, 0.f, 0.f, 0.f);
}

// ---------------------------------------------------------------------------
// One warp per interval. Lane l (0..19) owns channels [4l, 4l+4) as a float4.
// 16-point chunks:
//   - 1 LDG: lanes 0-15 read ranks_depth, lanes 16-31 read ranks_feat
//   - 1 LDG: lanes 0-15 gather the 16 depth scalars
//   - inner loop software-pipelined 4 points deep (4 independent LDG.128)
//   - next chunk's index/depth loads are prefetched one chunk ahead
// Intervals are disjoint BEV bins -> plain stores, no atomics.
// ---------------------------------------------------------------------------
__global__ void __launch_bounds__(256)
bev_pool_kernel(const float* __restrict__ depth,
                const float* __restrict__ feat,
                const int*   __restrict__ ranks_depth,
                const int*   __restrict__ ranks_feat,
                const int*   __restrict__ ranks_bev,
                const int*   __restrict__ istart,
                const int*   __restrict__ ilen,
                int n_intervals,
                float* __restrict__ out) {
    int gwarp = (blockIdx.x * blockDim.x + threadIdx.x) >> 5;
    int lane  = threadIdx.x & 31;
    if (gwarp >= n_intervals) return;

    const int start = istart[gwarp];
    const int len   = ilen[gwarp];

    const bool fa = (lane < 20);                 // feat-active lanes (20*4 = 80 ch)
    const float4* __restrict__ fbase = (const float4*)feat;

    float4 acc = make_float4(0.f, 0.f, 0.f, 0.f);

    const int lo16 = lane & 15;
    const int nfull = len & ~15;

    // ---- prefetch first chunk's indices + depth ----
    int   idxv = 0;
    float dv   = 0.f;
    if (nfull > 0) {
        const int* ip = (lane < 16) ? (ranks_depth + start + lane)
                                    : (ranks_feat  + start + lo16);
        idxv = __ldg(ip);
        if (lane < 16) dv = __ldg(&depth[idxv]);
    }

    for (int i = 0; i < nfull; i += 16) {
        // prefetch next chunk
        int   idxn = 0;
        float dn   = 0.f;
        if (i + 16 < nfull) {
            const int p = start + i + 16;
            const int* ip = (lane < 16) ? (ranks_depth + p + lane)
                                        : (ranks_feat  + p + lo16);
            idxn = __ldg(ip);
            if (lane < 16) dn = __ldg(&depth[idxn]);
        }

        #pragma unroll
        for (int j = 0; j < 16; j += 4) {
            // gather 4 points' scalars + row ids (full-warp shuffles)
            float d0 = __shfl_sync(0xffffffffu, dv, j + 0);
            float d1 = __shfl_sync(0xffffffffu, dv, j + 1);
            float d2 = __shfl_sync(0xffffffffu, dv, j + 2);
            float d3 = __shfl_sync(0xffffffffu, dv, j + 3);
            int rf0 = __shfl_sync(0xffffffffu, idxv, 16 + j + 0);
            int rf1 = __shfl_sync(0xffffffffu, idxv, 16 + j + 1);
            int rf2 = __shfl_sync(0xffffffffu, idxv, 16 + j + 2);
            int rf3 = __shfl_sync(0xffffffffu, idxv, 16 + j + 3);
            if (fa) {
                // 4 independent 128-bit gathers in flight
                float4 f0 = __ldg(fbase + (size_t)rf0 * 20 + lane);
                float4 f1 = __ldg(fbase + (size_t)rf1 * 20 + lane);
                float4 f2 = __ldg(fbase + (size_t)rf2 * 20 + lane);
                float4 f3 = __ldg(fbase + (size_t)rf3 * 20 + lane);
                acc.x = fmaf(d0, f0.x, acc.x);
                acc.y = fmaf(d0, f0.y, acc.y);
                acc.z = fmaf(d0, f0.z, acc.z);
                acc.w = fmaf(d0, f0.w, acc.w);
                acc.x = fmaf(d1, f1.x, acc.x);
                acc.y = fmaf(d1, f1.y, acc.y);
                acc.z = fmaf(d1, f1.z, acc.z);
                acc.w = fmaf(d1, f1.w, acc.w);
                acc.x = fmaf(d2, f2.x, acc.x);
                acc.y = fmaf(d2, f2.y, acc.y);
                acc.z = fmaf(d2, f2.z, acc.z);
                acc.w = fmaf(d2, f2.w, acc.w);
                acc.x = fmaf(d3, f3.x, acc.x);
                acc.y = fmaf(d3, f3.y, acc.y);
                acc.z = fmaf(d3, f3.z, acc.z);
                acc.w = fmaf(d3, f3.w, acc.w);
            }
        }

        idxv = idxn;
        dv   = dn;
    }

    // ---- tail chunk (< 16 points) ----
    if (nfull < len) {
        const int n = len - nfull;
        const int p = start + nfull;
        bool valid = lo16 < n;
        const int* ip = (lane < 16) ? (ranks_depth + p + lo16)
                                    : (ranks_feat  + p + lo16);
        int ti = valid ? __ldg(ip) : 0;
        float td = 0.f;
        if (lane < 16 && valid) td = __ldg(&depth[ti]);

        for (int j = 0; j < n; j++) {
            float d  = __shfl_sync(0xffffffffu, td, j);
            int   rf = __shfl_sync(0xffffffffu, ti, 16 + j);
            if (fa) {
                float4 f = __ldg(fbase + (size_t)rf * 20 + lane);
                acc.x = fmaf(d, f.x, acc.x);
                acc.y = fmaf(d, f.y, acc.y);
                acc.z = fmaf(d, f.z, acc.z);
                acc.w = fmaf(d, f.w, acc.w);
            }
        }
    }

    // ---- store: output layout (B, C, Dz, Dy, Dx); bev = b*S + s ----
    if (fa) {
        int bev = __ldg(&ranks_bev[start]);
        int b   = bev / S_;
        int s   = bev - b * S_;
        float* o = out + (size_t)b * C_ * S_ + s;
        int c = lane * 4;
        o[(size_t)(c + 0) * S_] = acc.x;
        o[(size_t)(c + 1) * S_] = acc.y;
        o[(size_t)(c + 2) * S_] = acc.z;
        o[(size_t)(c + 3) * S_] = acc.w;
    }
}

// ---------------------------------------------------------------------------
extern "C" void kernel_launch(void* const* d_in, const int* in_sizes, int n_in,
                              void* d_out, int out_size) {
    const float* depth = nullptr;
    const float* feat  = nullptr;
    const int*   ranks[3] = {nullptr, nullptr, nullptr};
    int nrk = 0;
    const int* small_arr[2] = {nullptr, nullptr};
    int small_sz[2] = {0, 0};
    int nsmall = 0;

    for (int i = 0; i < n_in; i++) {
        int sz = in_sizes[i];
        if (sz == N_DEPTH && !depth) {
            depth = (const float*)d_in[i];
        } else if (sz == N_FEAT && !feat) {
            feat = (const float*)d_in[i];
        } else if (sz == N_PTS && nrk < 3) {
            ranks[nrk++] = (const int*)d_in[i];   // order: depths, feats, bevs
        } else if (sz == 5) {
            // bev_feat_shape metadata — compile-time constants here
        } else if (nsmall < 2) {
            small_arr[nsmall] = (const int*)d_in[i];  // order: starts, lengths
            small_sz[nsmall] = sz;
            nsmall++;
        }
    }

    const int* istart = small_arr[0];
    const int* ilen   = small_arr[1];
    int n_intervals   = small_sz[0];

    float* out = (float*)d_out;

    // 1) zero the output
    int n4 = out_size / 4;
    zero_kernel<<<256, 256>>>((float4*)out, n4);

    // 2) pooled gather-multiply-store, one warp per interval
    const int threads = 256;                    // 8 warps per block
    int blocks = (n_intervals + 7) / 8;
    if (blocks < 1) blocks = 1;
    bev_pool_kernel<<<blocks, threads>>>(depth, feat,
                                         ranks[0], ranks[1], ranks[2],
                                         istart, ilen, n_intervals, out);
}

// round 5
// speedup vs baseline: 1.0102x; 1.0102x over previous
#include <cuda_runtime.h>
#include <cuda_bf16.h>

// Problem constants (fixed shapes for BevPoolV2_8478265442577)
#define B_     1
#define N_CAM  6
#define D_BINS 118
#define HF     32
#define WF     88
#define C_     80
#define DZ     1
#define DY     128
#define DX     128

#define N_DEPTH (B_ * N_CAM * D_BINS * HF * WF)   // 1,993,728
#define N_FEAT  (B_ * N_CAM * HF * WF * C_)       // 1,351,680
#define N_PTS   1000000
#define S_      (DZ * DY * DX)                    // 16,384

// ---------------------------------------------------------------------------
// Zero-init the output (harness poisons d_out with 0xAA; empty bins must be 0)
// ---------------------------------------------------------------------------
__global__ void zero_kernel(float4* __restrict__ out, int n4) {
    int i = blockIdx.x * blockDim.x + threadIdx.x;
    int stride = gridDim.x * blockDim.x;
    for (; i < n4; i += stride)
        out[i] = make_float4(0.f, 0.f, 0.f, 0.f);
}

// ---------------------------------------------------------------------------
// One warp per interval. Lane l (0..19) owns channels [4l, 4l+4) as a float4.
// 16-point chunks:
//   - 1 LDG: lanes 0-15 read ranks_depth, lanes 16-31 read ranks_feat
//   - 1 LDG: lanes 0-15 gather the 16 depth scalars
//   - inner loop software-pipelined 4 points deep (4 independent LDG.128)
//   - next chunk's index/depth loads are prefetched one chunk ahead
// Intervals are disjoint BEV bins -> plain stores, no atomics.
// ---------------------------------------------------------------------------
__global__ void __launch_bounds__(256)
bev_pool_kernel(const float* __restrict__ depth,
                const float* __restrict__ feat,
                const int*   __restrict__ ranks_depth,
                const int*   __restrict__ ranks_feat,
                const int*   __restrict__ ranks_bev,
                const int*   __restrict__ istart,
                const int*   __restrict__ ilen,
                int n_intervals,
                float* __restrict__ out) {
    int gwarp = (blockIdx.x * blockDim.x + threadIdx.x) >> 5;
    int lane  = threadIdx.x & 31;
    if (gwarp >= n_intervals) return;

    const int start = istart[gwarp];
    const int len   = ilen[gwarp];

    const bool fa = (lane < 20);                 // feat-active lanes (20*4 = 80 ch)
    const float4* __restrict__ fbase = (const float4*)feat;

    float4 acc = make_float4(0.f, 0.f, 0.f, 0.f);

    const int lo16 = lane & 15;
    const int nfull = len & ~15;

    // ---- prefetch first chunk's indices + depth ----
    int   idxv = 0;
    float dv   = 0.f;
    if (nfull > 0) {
        const int* ip = (lane < 16) ? (ranks_depth + start + lane)
                                    : (ranks_feat  + start + lo16);
        idxv = __ldg(ip);
        if (lane < 16) dv = __ldg(&depth[idxv]);
    }

    for (int i = 0; i < nfull; i += 16) {
        // prefetch next chunk
        int   idxn = 0;
        float dn   = 0.f;
        if (i + 16 < nfull) {
            const int p = start + i + 16;
            const int* ip = (lane < 16) ? (ranks_depth + p + lane)
                                        : (ranks_feat  + p + lo16);
            idxn = __ldg(ip);
            if (lane < 16) dn = __ldg(&depth[idxn]);
        }

        #pragma unroll
        for (int j = 0; j < 16; j += 4) {
            // gather 4 points' scalars + row ids (full-warp shuffles)
            float d0 = __shfl_sync(0xffffffffu, dv, j + 0);
            float d1 = __shfl_sync(0xffffffffu, dv, j + 1);
            float d2 = __shfl_sync(0xffffffffu, dv, j + 2);
            float d3 = __shfl_sync(0xffffffffu, dv, j + 3);
            int rf0 = __shfl_sync(0xffffffffu, idxv, 16 + j + 0);
            int rf1 = __shfl_sync(0xffffffffu, idxv, 16 + j + 1);
            int rf2 = __shfl_sync(0xffffffffu, idxv, 16 + j + 2);
            int rf3 = __shfl_sync(0xffffffffu, idxv, 16 + j + 3);
            if (fa) {
                // 4 independent 128-bit gathers in flight
                float4 f0 = __ldg(fbase + (size_t)rf0 * 20 + lane);
                float4 f1 = __ldg(fbase + (size_t)rf1 * 20 + lane);
                float4 f2 = __ldg(fbase + (size_t)rf2 * 20 + lane);
                float4 f3 = __ldg(fbase + (size_t)rf3 * 20 + lane);
                acc.x = fmaf(d0, f0.x, acc.x);
                acc.y = fmaf(d0, f0.y, acc.y);
                acc.z = fmaf(d0, f0.z, acc.z);
                acc.w = fmaf(d0, f0.w, acc.w);
                acc.x = fmaf(d1, f1.x, acc.x);
                acc.y = fmaf(d1, f1.y, acc.y);
                acc.z = fmaf(d1, f1.z, acc.z);
                acc.w = fmaf(d1, f1.w, acc.w);
                acc.x = fmaf(d2, f2.x, acc.x);
                acc.y = fmaf(d2, f2.y, acc.y);
                acc.z = fmaf(d2, f2.z, acc.z);
                acc.w = fmaf(d2, f2.w, acc.w);
                acc.x = fmaf(d3, f3.x, acc.x);
                acc.y = fmaf(d3, f3.y, acc.y);
                acc.z = fmaf(d3, f3.z, acc.z);
                acc.w = fmaf(d3, f3.w, acc.w);
            }
        }

        idxv = idxn;
        dv   = dn;
    }

    // ---- tail chunk (< 16 points) ----
    if (nfull < len) {
        const int n = len - nfull;
        const int p = start + nfull;
        bool valid = lo16 < n;
        const int* ip = (lane < 16) ? (ranks_depth + p + lo16)
                                    : (ranks_feat  + p + lo16);
        int ti = valid ? __ldg(ip) : 0;
        float td = 0.f;
        if (lane < 16 && valid) td = __ldg(&depth[ti]);

        for (int j = 0; j < n; j++) {
            float d  = __shfl_sync(0xffffffffu, td, j);
            int   rf = __shfl_sync(0xffffffffu, ti, 16 + j);
            if (fa) {
                float4 f = __ldg(fbase + (size_t)rf * 20 + lane);
                acc.x = fmaf(d, f.x, acc.x);
                acc.y = fmaf(d, f.y, acc.y);
                acc.z = fmaf(d, f.z, acc.z);
                acc.w = fmaf(d, f.w, acc.w);
            }
        }
    }

    // ---- store: output layout (B, C, Dz, Dy, Dx); bev = b*S + s ----
    if (fa) {
        int bev = __ldg(&ranks_bev[start]);
        int b   = bev / S_;
        int s   = bev - b * S_;
        float* o = out + (size_t)b * C_ * S_ + s;
        int c = lane * 4;
        o[(size_t)(c + 0) * S_] = acc.x;
        o[(size_t)(c + 1) * S_] = acc.y;
        o[(size_t)(c + 2) * S_] = acc.z;
        o[(size_t)(c + 3) * S_] = acc.w;
    }
}

// ---------------------------------------------------------------------------
extern "C" void kernel_launch(void* const* d_in, const int* in_sizes, int n_in,
                              void* d_out, int out_size) {
    const float* depth = nullptr;
    const float* feat  = nullptr;
    const int*   ranks[3] = {nullptr, nullptr, nullptr};
    int nrk = 0;
    const int* small_arr[2] = {nullptr, nullptr};
    int small_sz[2] = {0, 0};
    int nsmall = 0;

    for (int i = 0; i < n_in; i++) {
        int sz = in_sizes[i];
        if (sz == N_DEPTH && !depth) {
            depth = (const float*)d_in[i];
        } else if (sz == N_FEAT && !feat) {
            feat = (const float*)d_in[i];
        } else if (sz == N_PTS && nrk < 3) {
            ranks[nrk++] = (const int*)d_in[i];   // order: depths, feats, bevs
        } else if (sz == 5) {
            // bev_feat_shape metadata — compile-time constants here
        } else if (nsmall < 2) {
            small_arr[nsmall] = (const int*)d_in[i];  // order: starts, lengths
            small_sz[nsmall] = sz;
            nsmall++;
        }
    }

    const int* istart = small_arr[0];
    const int* ilen   = small_arr[1];
    int n_intervals   = small_sz[0];

    float* out = (float*)d_out;

    // 1) zero the output
    int n4 = out_size / 4;
    zero_kernel<<<256, 256>>>((float4*)out, n4);

    // 2) pooled gather-multiply-store, one warp per interval
    const int threads = 256;                    // 8 warps per block
    int blocks = (n_intervals + 7) / 8;
    if (blocks < 1) blocks = 1;
    bev_pool_kernel<<<blocks, threads>>>(depth, feat,
                                         ranks[0], ranks[1], ranks[2],
                                         istart, ilen, n_intervals, out);
}

// round 6
// speedup vs baseline: 1.0457x; 1.0351x over previous
#include <cuda_runtime.h>
#include <cuda_bf16.h>

// Problem constants (fixed shapes for BevPoolV2_8478265442577)
#define B_     1
#define N_CAM  6
#define D_BINS 118
#define HF     32
#define WF     88
#define C_     80
#define DZ     1
#define DY     128
#define DX     128

#define N_DEPTH (B_ * N_CAM * D_BINS * HF * WF)   // 1,993,728
#define N_FEAT  (B_ * N_CAM * HF * WF * C_)       // 1,351,680
#define N_PTS   1000000
#define S_      (DZ * DY * DX)                    // 16,384

// ---------------------------------------------------------------------------
// Zero-init the output (harness poisons d_out with 0xAA; empty bins must be 0)
// ---------------------------------------------------------------------------
__global__ void zero_kernel(float4* __restrict__ out, int n4) {
    int i = blockIdx.x * blockDim.x + threadIdx.x;
    int stride = gridDim.x * blockDim.x;
    for (; i < n4; i += stride)
        out[i] = make_float4(0.f, 0.f, 0.f, 0.f);
}

// ---------------------------------------------------------------------------
// One warp per interval. Lane l (0..19) owns channels [4l, 4l+4) as a float4.
// Per 16-point chunk:
//   - 1 LDG: lanes 0-15 read ranks_depth, lanes 16-31 read ranks_feat
//   - 1 LDG: lanes 0-15 gather the 16 depth scalars
//   - stage (depth, rank_feat) pairs in per-warp smem (2 STS)
//   - broadcast-read pairs via LDS.128 (independent loads -> real MLP),
//     4 feat LDG.128 in flight per group of 4 points
// Intervals are disjoint BEV bins -> plain stores, no atomics.
// ---------------------------------------------------------------------------
__global__ void __launch_bounds__(256)
bev_pool_kernel(const float* __restrict__ depth,
                const float* __restrict__ feat,
                const int*   __restrict__ ranks_depth,
                const int*   __restrict__ ranks_feat,
                const int*   __restrict__ ranks_bev,
                const int*   __restrict__ istart,
                const int*   __restrict__ ilen,
                int n_intervals,
                float* __restrict__ out) {
    // per-warp staging: 16 (float d, int rf) pairs = 128 B
    __shared__ float4 sbuf[8][8];   // [warp][8 x float4] = 16 pairs

    const int wslot = threadIdx.x >> 5;
    const int lane  = threadIdx.x & 31;
    const int gwarp = (blockIdx.x * blockDim.x + threadIdx.x) >> 5;
    if (gwarp >= n_intervals) return;

    const int start = istart[gwarp];
    const int len   = ilen[gwarp];

    const bool fa = (lane < 20);                 // feat-active lanes (20*4 = 80 ch)
    const float4* __restrict__ fbase = (const float4*)feat;
    float* sb = (float*)&sbuf[wslot][0];         // 32 floats: [2j]=d_j, [2j+1]=rf_j

    float4 acc = make_float4(0.f, 0.f, 0.f, 0.f);

    const int lo16  = lane & 15;
    const int nfull = len & ~15;

    for (int i = 0; i < nfull; i += 16) {
        const int p = start + i;
        // lanes 0-15: ranks_depth; lanes 16-31: ranks_feat
        const int* ip = (lane < 16) ? (ranks_depth + p + lane)
                                    : (ranks_feat  + p + lo16);
        const int idxv = __ldg(ip);
        // stage: lanes 0-15 write depth scalar, lanes 16-31 write feat row id
        if (lane < 16) sb[2 * lo16]     = __ldg(&depth[idxv]);
        else           sb[2 * lo16 + 1] = __int_as_float(idxv);
        __syncwarp();

        #pragma unroll
        for (int j = 0; j < 16; j += 4) {
            // broadcast-read 4 (d, rf) pairs -- 2 independent LDS.128
            float4 q0 = sbuf[wslot][j / 2];      // pairs j, j+1
            float4 q1 = sbuf[wslot][j / 2 + 1];  // pairs j+2, j+3
            int rf0 = __float_as_int(q0.y);
            int rf1 = __float_as_int(q0.w);
            int rf2 = __float_as_int(q1.y);
            int rf3 = __float_as_int(q1.w);
            if (fa) {
                // 4 independent 128-bit gathers in flight
                float4 f0 = __ldg(fbase + (size_t)rf0 * 20 + lane);
                float4 f1 = __ldg(fbase + (size_t)rf1 * 20 + lane);
                float4 f2 = __ldg(fbase + (size_t)rf2 * 20 + lane);
                float4 f3 = __ldg(fbase + (size_t)rf3 * 20 + lane);
                acc.x = fmaf(q0.x, f0.x, acc.x);
                acc.y = fmaf(q0.x, f0.y, acc.y);
                acc.z = fmaf(q0.x, f0.z, acc.z);
                acc.w = fmaf(q0.x, f0.w, acc.w);
                acc.x = fmaf(q0.z, f1.x, acc.x);
                acc.y = fmaf(q0.z, f1.y, acc.y);
                acc.z = fmaf(q0.z, f1.z, acc.z);
                acc.w = fmaf(q0.z, f1.w, acc.w);
                acc.x = fmaf(q1.x, f2.x, acc.x);
                acc.y = fmaf(q1.x, f2.y, acc.y);
                acc.z = fmaf(q1.x, f2.z, acc.z);
                acc.w = fmaf(q1.x, f2.w, acc.w);
                acc.x = fmaf(q1.z, f3.x, acc.x);
                acc.y = fmaf(q1.z, f3.y, acc.y);
                acc.z = fmaf(q1.z, f3.z, acc.z);
                acc.w = fmaf(q1.z, f3.w, acc.w);
            }
        }
        __syncwarp();   // all lanes done reading before next chunk's STS
    }

    // ---- tail chunk (< 16 points): shuffle path, rare ----
    if (nfull < len) {
        const int n = len - nfull;
        const int p = start + nfull;
        bool valid = lo16 < n;
        const int* ip = (lane < 16) ? (ranks_depth + p + lo16)
                                    : (ranks_feat  + p + lo16);
        int ti = valid ? __ldg(ip) : 0;
        float td = 0.f;
        if (lane < 16 && valid) td = __ldg(&depth[ti]);

        for (int j = 0; j < n; j++) {
            float d  = __shfl_sync(0xffffffffu, td, j);
            int   rf = __shfl_sync(0xffffffffu, ti, 16 + j);
            if (fa) {
                float4 f = __ldg(fbase + (size_t)rf * 20 + lane);
                acc.x = fmaf(d, f.x, acc.x);
                acc.y = fmaf(d, f.y, acc.y);
                acc.z = fmaf(d, f.z, acc.z);
                acc.w = fmaf(d, f.w, acc.w);
            }
        }
    }

    // ---- store: output layout (B, C, Dz, Dy, Dx); bev = b*S + s ----
    if (fa) {
        int bev = __ldg(&ranks_bev[start]);
        int b   = bev / S_;
        int s   = bev - b * S_;
        float* o = out + (size_t)b * C_ * S_ + s;
        int c = lane * 4;
        o[(size_t)(c + 0) * S_] = acc.x;
        o[(size_t)(c + 1) * S_] = acc.y;
        o[(size_t)(c + 2) * S_] = acc.z;
        o[(size_t)(c + 3) * S_] = acc.w;
    }
}

// ---------------------------------------------------------------------------
extern "C" void kernel_launch(void* const* d_in, const int* in_sizes, int n_in,
                              void* d_out, int out_size) {
    const float* depth = nullptr;
    const float* feat  = nullptr;
    const int*   ranks[3] = {nullptr, nullptr, nullptr};
    int nrk = 0;
    const int* small_arr[2] = {nullptr, nullptr};
    int small_sz[2] = {0, 0};
    int nsmall = 0;

    for (int i = 0; i < n_in; i++) {
        int sz = in_sizes[i];
        if (sz == N_DEPTH && !depth) {
            depth = (const float*)d_in[i];
        } else if (sz == N_FEAT && !feat) {
            feat = (const float*)d_in[i];
        } else if (sz == N_PTS && nrk < 3) {
            ranks[nrk++] = (const int*)d_in[i];   // order: depths, feats, bevs
        } else if (sz == 5) {
            // bev_feat_shape metadata — compile-time constants here
        } else if (nsmall < 2) {
            small_arr[nsmall] = (const int*)d_in[i];  // order: starts, lengths
            small_sz[nsmall] = sz;
            nsmall++;
        }
    }

    const int* istart = small_arr[0];
    const int* ilen   = small_arr[1];
    int n_intervals   = small_sz[0];

    float* out = (float*)d_out;

    // 1) zero the output
    int n4 = out_size / 4;
    zero_kernel<<<256, 256>>>((float4*)out, n4);

    // 2) pooled gather-multiply-store, one warp per interval
    const int threads = 256;                    // 8 warps per block
    int blocks = (n_intervals + 7) / 8;
    if (blocks < 1) blocks = 1;
    bev_pool_kernel<<<blocks, threads>>>(depth, feat,
                                         ranks[0], ranks[1], ranks[2],
                                         istart, ilen, n_intervals, out);
}